// round 8
// baseline (speedup 1.0000x reference)
#include <cuda_runtime.h>

// HeadProbEncoder: B=8, L=512, d=64, n_head=12, K=2 triangles, 4 iterations.
// Round 7: broadcast-free f32x2 GEMMs via pre-duplicated operand arrays.
// Inner step = 4 LDS.128 + 16 FFMA2, zero MOVs. smem 102KB -> 2 blocks/SM.

#define BB 8
#define LL 512
#define DD 64
#define HH 12
#define NROW (BB*LL)
#define NELT (BB*LL*DD)
#define SA 68      // stride (floats) for non-dup tiles
#define SD 136     // stride (floats) for duplicated tiles (128 data + 8 pad)

typedef unsigned long long u64;

// -------- scratch --------
__device__ float g_Pt   [BB*DD*LL];       // [z][b][i]           (prologue a-operand)
__device__ float g_Ptdup[BB*DD*2*LL];     // [z][b][2j] dup      (S GEMM b-operand)
__device__ float g_Pdup [BB*LL*2*DD];     // [z][j][2b] dup      (W GEMM b-operand)
__device__ float g_Trdup [2*HH*DD*2*DD];  // [kc][a][2b] dup     (A GEMM b-operand)
__device__ float g_Trtdup[2*HH*DD*2*DD];  // [kc][b][2a] dup     (G GEMM b-operand)
__device__ float g_Gpart[HH*NELT];        // per-c G partials

__device__ __forceinline__ u64 pk2(float lo, float hi){ u64 r; asm("mov.b64 %0,{%1,%2};":"=l"(r):"f"(lo),"f"(hi)); return r; }
__device__ __forceinline__ void f2(u64 &d, u64 a, u64 b){ asm("fma.rn.f32x2 %0,%1,%2,%0;":"+l"(d):"l"(a),"l"(b)); }
__device__ __forceinline__ void m2(u64 &d, u64 s){ asm("mul.rn.f32x2 %0,%0,%1;":"+l"(d):"l"(s)); }
__device__ __forceinline__ float2 up2(u64 v){ float2 f; asm("mov.b64 {%0,%1},%2;":"=f"(f.x),"=f"(f.y):"l"(v)); return f; }
__device__ __forceinline__ unsigned smaddr(const void* p){ return (unsigned)__cvta_generic_to_shared(p); }
__device__ __forceinline__ void cpa16(unsigned s, const void* g){ asm volatile("cp.async.cg.shared.global [%0],[%1],16;"::"r"(s),"l"(g):"memory"); }
__device__ __forceinline__ void cpcommit(){ asm volatile("cp.async.commit_group;":::"memory"); }
__device__ __forceinline__ void cpwait0(){ asm volatile("cp.async.wait_group 0;":::"memory"); }
__device__ __forceinline__ void cpwait1(){ asm volatile("cp.async.wait_group 1;":::"memory"); }

#define STEP4(ACC,P0,P1,P2,P3,B0,B1,B2,B3) do{ \
  f2(ACC[0][0],P0,B0); f2(ACC[0][1],P0,B1); f2(ACC[0][2],P0,B2); f2(ACC[0][3],P0,B3); \
  f2(ACC[1][0],P1,B0); f2(ACC[1][1],P1,B1); f2(ACC[1][2],P1,B2); f2(ACC[1][3],P1,B3); \
  f2(ACC[2][0],P2,B0); f2(ACC[2][1],P2,B1); f2(ACC[2][2],P2,B2); f2(ACC[2][3],P2,B3); \
  f2(ACC[3][0],P3,B0); f2(ACC[3][1],P3,B1); f2(ACC[3][2],P3,B2); f2(ACC[3][3],P3,B3); \
} while(0)

// GEMM step: a-pairs from tile As (stride SA), dup b-operands from Bd (stride SD)
#define GSTEP(ACC, As, Bd, row) do{ \
  ulonglong2 _a01 = *(const ulonglong2*)&(As)[(row)*SA + ty*8]; \
  ulonglong2 _a23 = *(const ulonglong2*)&(As)[(row)*SA + ty*8 + 4]; \
  ulonglong2 _b01 = *(const ulonglong2*)&(Bd)[(row)*SD + tx*8]; \
  ulonglong2 _b23 = *(const ulonglong2*)&(Bd)[(row)*SD + tx*8 + 4]; \
  STEP4(ACC, _a01.x, _a01.y, _a23.x, _a23.y, _b01.x, _b01.y, _b23.x, _b23.y); \
} while(0)

// -------- K0: rearrange ternary into duplicated layouts --------
__global__ void k_prep_T(const float* __restrict__ ternary) {
    int idx = blockIdx.x * blockDim.x + threadIdx.x;
    if (idx >= 2*DD*DD*HH) return;
    int c = idx % HH; int t = idx / HH;
    int b = t % DD;   t /= DD;
    int a = t % DD;   int k = t / DD;
    float v = 64.0f * ternary[idx];
    int kc = k*HH + c;
    ((float2*)g_Trdup )[(kc*DD + a)*DD + b] = make_float2(v, v);
    ((float2*)g_Trtdup)[(kc*DD + b)*DD + a] = make_float2(v, v);
}

// -------- K1: p = softmax_d(q_z)*mask; writes Pt + dup arrays --------
__global__ void k_softmax_p(const float* __restrict__ x, const int* __restrict__ mask, int use_g) {
    int gw = (blockIdx.x * blockDim.x + threadIdx.x) >> 5;
    int lane = threadIdx.x & 31;
    if (gw >= NROW) return;
    int base = gw * DD;
    float v0 = x[base + lane], v1 = x[base + lane + 32];
    if (use_g) {
        #pragma unroll
        for (int g = 0; g < HH; g++) {
            v0 += g_Gpart[g*NELT + base + lane];
            v1 += g_Gpart[g*NELT + base + lane + 32];
        }
        v0 *= (1.0f/64.0f); v1 *= (1.0f/64.0f);
    }
    float m = fmaxf(v0, v1);
    #pragma unroll
    for (int off = 16; off; off >>= 1) m = fmaxf(m, __shfl_xor_sync(0xffffffffu, m, off));
    float e0 = __expf(v0 - m), e1 = __expf(v1 - m);
    float s = e0 + e1;
    #pragma unroll
    for (int off = 16; off; off >>= 1) s += __shfl_xor_sync(0xffffffffu, s, off);
    float mm = (mask[gw] != 0) ? 1.0f : 0.0f;
    float inv = mm / s;
    float p0 = e0 * inv, p1 = e1 * inv;
    int z = gw >> 9, i = gw & 511;
    g_Pt[(z*DD + lane     )*LL + i] = p0;
    g_Pt[(z*DD + lane + 32)*LL + i] = p1;
    ((float2*)g_Ptdup)[(z*DD + lane     )*LL + i] = make_float2(p0, p0);
    ((float2*)g_Ptdup)[(z*DD + lane + 32)*LL + i] = make_float2(p1, p1);
    ((float2*)g_Pdup )[(z*LL + i)*DD + lane     ] = make_float2(p0, p0);
    ((float2*)g_Pdup )[(z*LL + i)*DD + lane + 32] = make_float2(p1, p1);
}

// -------- K2: fused per-(z,c,i0), two triangle passes, dup operands --------
extern __shared__ float smf[];
__global__ void __launch_bounds__(128, 2) k_fused() {
    float* sA = smf;             // A tile [b][i] SA       (later: W_U)
    float* R0 = smf + 64*SA;     // Tdup / Pjdup / TrtUdup (stride SD)
    float* R1 = smf + 64*SA + 64*SD;   // Pt / E [j][i] SA (later: W_L)
    float* sV = smf + 2*64*SA + 64*SD; // Vdup / TrtLdup   (stride SD)
    int i0 = blockIdx.x*64, c = blockIdx.y, z = blockIdx.z;
    int it = blockIdx.x;
    int tid = threadIdx.x, tx = tid & 15, ty = tid >> 4;

    float m[8], ss[8];
    #pragma unroll
    for (int r = 0; r < 8; r++) { m[r] = -1e30f; ss[r] = 0.0f; }
    u64 aU[4][4] = {}, aL[4][4] = {};

    #pragma unroll
    for (int pass = 0; pass < 2; pass++) {
        // ---- A prep: A = Pt_tile @ T[pass?HH+c:c]
        const float* Tsrc = &g_Trdup[(pass ? HH + c : c)*DD*2*DD];
        for (int t = tid; t < 2048; t += 128) {
            int r = t >> 5, q = (t & 31) << 2;
            cpa16(smaddr(&R0[r*SD+q]), &Tsrc[r*128 + q]);
        }
        for (int t = tid; t < 1024; t += 128) {
            int r = t >> 4, q = (t & 15) << 2;
            cpa16(smaddr(&R1[r*SA+q]), &g_Pt[(z*DD + r)*LL + i0 + q]);
        }
        cpcommit(); cpwait0(); __syncthreads();
        {
            u64 acc[4][4] = {};
            #pragma unroll 8
            for (int a = 0; a < 64; a++) GSTEP(acc, R1, R0, a);
            __syncthreads();     // reads done; sA overwrite safe
            #pragma unroll
            for (int s = 0; s < 4; s++) {
                float* dst = &sA[(tx*4+s)*SA + ty*8];
                ((ulonglong2*)dst)[0] = make_ulonglong2(acc[0][s], acc[1][s]);
                ((ulonglong2*)dst)[1] = make_ulonglong2(acc[2][s], acc[3][s]);
            }
        }
        __syncthreads();

        int jbeg = pass ? 0 : it;
        int jend = pass ? it : 7;
        for (int t = tid; t < 2048; t += 128) {     // Pjdup[jbeg] (own group)
            int r = t >> 5, q = (t & 31) << 2;
            cpa16(smaddr(&R0[r*SD+q]), &g_Ptdup[(z*DD + r)*2*LL + jbeg*128 + q]);
        }
        cpcommit();
        for (int t = tid; t < 2048; t += 128) {     // Vdup[jbeg] (own group)
            int r = t >> 5, q = (t & 31) << 2;
            cpa16(smaddr(&sV[r*SD+q]), &g_Pdup[(z*LL + jbeg*64 + r)*2*DD + q]);
        }
        cpcommit();

        u64 (*aT)[4] = pass ? aL : aU;
        #pragma unroll 1
        for (int jt = jbeg; jt <= jend; jt++) {
            cpwait1(); __syncthreads();             // Pjdup[jt] ready

            // ---- S GEMM
            u64 acc[4][4] = {};
            #pragma unroll 8
            for (int b = 0; b < 64; b++) GSTEP(acc, sA, R0, b);
            __syncthreads();                        // done reading R0
            bool pjnext = (jt < jend);
            if (pjnext) {
                for (int t = tid; t < 2048; t += 128) {
                    int r = t >> 5, q = (t & 31) << 2;
                    cpa16(smaddr(&R0[r*SD+q]), &g_Ptdup[(z*DD + r)*2*LL + (jt+1)*128 + q]);
                }
                cpcommit();
            }

            // ---- flash update + E write (diag tiles masked per pass)
            bool dg = (jt == it);
            float scv[8];
            #pragma unroll
            for (int rp = 0; rp < 4; rp++) {
                #pragma unroll
                for (int rr = 0; rr < 2; rr++) {
                    int r = rp*2 + rr;
                    int gi = ty*8 + r;
                    float vv[4];
                    #pragma unroll
                    for (int s = 0; s < 4; s++) {
                        float2 f = up2(acc[rp][s]);
                        vv[s] = rr ? f.y : f.x;
                    }
                    if (dg) {
                        #pragma unroll
                        for (int s = 0; s < 4; s++) {
                            int gj = tx*4 + s;
                            if (pass == 0) vv[s] = (gj > gi) ? vv[s] : (gj == gi ? 0.0f : -1e30f);
                            else           vv[s] = (gj < gi) ? vv[s] : -1e30f;
                        }
                    }
                    float tm = fmaxf(fmaxf(vv[0], vv[1]), fmaxf(vv[2], vv[3]));
                    #pragma unroll
                    for (int off = 1; off < 16; off <<= 1)
                        tm = fmaxf(tm, __shfl_xor_sync(0xffffffffu, tm, off));
                    float nm = fmaxf(m[r], tm);
                    float sc = __expf(m[r] - nm);
                    float e0 = __expf(vv[0]-nm), e1 = __expf(vv[1]-nm);
                    float e2 = __expf(vv[2]-nm), e3 = __expf(vv[3]-nm);
                    ss[r] = ss[r]*sc + e0+e1+e2+e3;
                    m[r] = nm; scv[r] = sc;
                    if (dg && pass == 0) {          // j==i in normalizer, not in W
                        if (tx*4+0 == gi) e0 = 0.0f;
                        if (tx*4+1 == gi) e1 = 0.0f;
                        if (tx*4+2 == gi) e2 = 0.0f;
                        if (tx*4+3 == gi) e3 = 0.0f;
                    }
                    int ic = gi ^ ((tx & 3) << 3);  // XOR swizzle
                    R1[(tx*4+0)*SA + ic] = e0;
                    R1[(tx*4+1)*SA + ic] = e1;
                    R1[(tx*4+2)*SA + ic] = e2;
                    R1[(tx*4+3)*SA + ic] = e3;
                }
            }
            // rescale both W accumulators
            #pragma unroll
            for (int rp = 0; rp < 4; rp++) {
                u64 sc2 = pk2(scv[2*rp], scv[2*rp+1]);
                #pragma unroll
                for (int s = 0; s < 4; s++) { m2(aU[rp][s], sc2); m2(aL[rp][s], sc2); }
            }
            if (pjnext) cpwait1(); else cpwait0();  // Vdup[jt] ready
            __syncthreads();                        // E visible + V visible

            // ---- W GEMM: E @ V -> aT (E i-pairs with swizzle, V dup)
            #pragma unroll 8
            for (int j = 0; j < 64; j++) {
                int base = (ty*8) ^ (((j >> 2) & 3) << 3);
                ulonglong2 p01 = *(const ulonglong2*)&R1[j*SA + base];
                ulonglong2 p23 = *(const ulonglong2*)&R1[j*SA + base + 4];
                ulonglong2 b01 = *(const ulonglong2*)&sV[j*SD + tx*8];
                ulonglong2 b23 = *(const ulonglong2*)&sV[j*SD + tx*8 + 4];
                STEP4(aT, p01.x, p01.y, p23.x, p23.y, b01.x, b01.y, b23.x, b23.y);
            }
            __syncthreads();                        // done reading sV, R1
            if (jt < jend) {
                for (int t = tid; t < 2048; t += 128) {
                    int r = t >> 5, q = (t & 31) << 2;
                    cpa16(smaddr(&sV[r*SD+q]), &g_Pdup[(z*LL + (jt+1)*64 + r)*2*DD + q]);
                }
                cpcommit();
            }
        }
    }

    // ---- normalize W by 1/sum_exp
    #pragma unroll
    for (int r = 0; r < 8; r++) {
        float sr = ss[r];
        #pragma unroll
        for (int off = 1; off < 16; off <<= 1)
            sr += __shfl_xor_sync(0xffffffffu, sr, off);
        ss[r] = 1.0f / sr;
    }
    #pragma unroll
    for (int rp = 0; rp < 4; rp++) {
        u64 iv2 = pk2(ss[2*rp], ss[2*rp+1]);
        #pragma unroll
        for (int s = 0; s < 4; s++) { m2(aU[rp][s], iv2); m2(aL[rp][s], iv2); }
    }

    // ---- epilogue: G_c = W_U @ Trt[c] + W_L @ Trt[HH+c]
    // issue dup Trt loads into R0 / sV (both free), store W tiles meanwhile
    for (int t = tid; t < 2048; t += 128) {
        int r = t >> 5, q = (t & 31) << 2;
        cpa16(smaddr(&R0[r*SD+q]), &g_Trtdup[((c   )*DD + r)*128 + q]);
        cpa16(smaddr(&sV[r*SD+q]), &g_Trtdup[((HH+c)*DD + r)*128 + q]);
    }
    cpcommit();
    #pragma unroll
    for (int s = 0; s < 4; s++) {
        float* dU = &sA[(tx*4+s)*SA + ty*8];
        ((ulonglong2*)dU)[0] = make_ulonglong2(aU[0][s], aU[1][s]);
        ((ulonglong2*)dU)[1] = make_ulonglong2(aU[2][s], aU[3][s]);
        float* dL = &R1[(tx*4+s)*SA + ty*8];
        ((ulonglong2*)dL)[0] = make_ulonglong2(aL[0][s], aL[1][s]);
        ((ulonglong2*)dL)[1] = make_ulonglong2(aL[2][s], aL[3][s]);
    }
    cpwait0(); __syncthreads();
    u64 acc[4][4] = {};
    #pragma unroll 4
    for (int b = 0; b < 64; b++) {
        GSTEP(acc, sA, R0, b);
        GSTEP(acc, R1, sV, b);
    }
    #pragma unroll
    for (int rp = 0; rp < 4; rp++) {
        float2 x0 = up2(acc[rp][0]), x1 = up2(acc[rp][1]);
        float2 x2 = up2(acc[rp][2]), x3 = up2(acc[rp][3]);
        int i = i0 + ty*8 + rp*2;
        *(float4*)&g_Gpart[(c*NROW + z*LL + i    )*DD + tx*4] = make_float4(x0.x, x1.x, x2.x, x3.x);
        *(float4*)&g_Gpart[(c*NROW + z*LL + i + 1)*DD + tx*4] = make_float4(x0.y, x1.y, x2.y, x3.y);
    }
}

// -------- K3: out = (x + sum Gpart) / 64 --------
__global__ void k_final(const float* __restrict__ x, float* __restrict__ out) {
    int idx = blockIdx.x * blockDim.x + threadIdx.x;
    if (idx >= NELT) return;
    float v = x[idx];
    #pragma unroll
    for (int g = 0; g < HH; g++) v += g_Gpart[g*NELT + idx];
    out[idx] = v * (1.0f/64.0f);
}

extern "C" void kernel_launch(void* const* d_in, const int* in_sizes, int n_in,
                              void* d_out, int out_size) {
    const float* x       = (const float*)d_in[0];
    const int*   mask    = (const int*)d_in[1];
    const float* ternary = (const float*)d_in[2];
    for (int i = 0; i < n_in; i++) {
        if      (in_sizes[i] == NELT)        x       = (const float*)d_in[i];
        else if (in_sizes[i] == BB*LL)       mask    = (const int*)d_in[i];
        else if (in_sizes[i] == 2*DD*DD*HH)  ternary = (const float*)d_in[i];
    }
    const int SMEM_F = (2*64*SA + 2*64*SD) * 4;   // 104448 B -> 2 blocks/SM
    cudaFuncSetAttribute(k_fused, cudaFuncAttributeMaxDynamicSharedMemorySize, SMEM_F);

    k_prep_T<<<96, 1024>>>(ternary);
    for (int it = 0; it < 4; it++) {
        k_softmax_p<<<NROW/4, 128>>>(x, mask, it > 0 ? 1 : 0);
        k_fused<<<dim3(8, HH, BB), 128, SMEM_F>>>();
    }
    k_final<<<(NELT + 255)/256, 256>>>(x, (float*)d_out);
}

// round 13
// speedup vs baseline: 1.5285x; 1.5285x over previous
#include <cuda_runtime.h>

// HeadProbEncoder: B=8, L=512, d=64, n_head=12, K=2 triangles, 4 iterations.
// Round 12 resubmit (infra failed twice): round-6 online-softmax algorithm
// with 128-row i-tiles and 256 threads: per-thread code identical, tile-event
// overhead (loads/exps/shuffles/barriers) per unit GEMM cut ~45%. 16 warps/SM.

#define BB 8
#define LL 512
#define DD 64
#define HH 12
#define NROW (BB*LL)
#define NELT (BB*LL*DD)
#define SA 68      // stride for 64-wide tiles (Pj, V, Trt)
#define SI 132     // stride for 128-wide tiles (A, E/Pt, W)

typedef unsigned long long u64;

// -------- scratch --------
__device__ float g_P [NELT];          // [z][i][b]
__device__ float g_Pt[BB*DD*LL];      // [z][b][i]
__device__ float g_Tr [2*HH*DD*DD];   // [kc][a][b]
__device__ float g_Trt[2*HH*DD*DD];   // [kc][b][a]
__device__ float g_Gpart[HH*NELT];    // per-c G partials

__device__ __forceinline__ u64 bc2(float v){ u64 r; asm("mov.b64 %0,{%1,%1};":"=l"(r):"f"(v)); return r; }
__device__ __forceinline__ u64 pk2(float lo, float hi){ u64 r; asm("mov.b64 %0,{%1,%2};":"=l"(r):"f"(lo),"f"(hi)); return r; }
__device__ __forceinline__ void f2(u64 &d, u64 a, u64 b){ asm("fma.rn.f32x2 %0,%1,%2,%0;":"+l"(d):"l"(a),"l"(b)); }
__device__ __forceinline__ void m2(u64 &d, u64 s){ asm("mul.rn.f32x2 %0,%0,%1;":"+l"(d):"l"(s)); }
__device__ __forceinline__ float2 up2(u64 v){ float2 f; asm("mov.b64 {%0,%1},%2;":"=f"(f.x),"=f"(f.y):"l"(v)); return f; }
__device__ __forceinline__ unsigned smaddr(const void* p){ return (unsigned)__cvta_generic_to_shared(p); }
__device__ __forceinline__ void cpa16(unsigned s, const void* g){ asm volatile("cp.async.cg.shared.global [%0],[%1],16;"::"r"(s),"l"(g):"memory"); }
__device__ __forceinline__ void cpcommit(){ asm volatile("cp.async.commit_group;":::"memory"); }
__device__ __forceinline__ void cpwait0(){ asm volatile("cp.async.wait_group 0;":::"memory"); }
__device__ __forceinline__ void cpwait1(){ asm volatile("cp.async.wait_group 1;":::"memory"); }

#define STEP4(ACC,P0,P1,P2,P3,B0,B1,B2,B3) do{ \
  f2(ACC[0][0],P0,B0); f2(ACC[0][1],P0,B1); f2(ACC[0][2],P0,B2); f2(ACC[0][3],P0,B3); \
  f2(ACC[1][0],P1,B0); f2(ACC[1][1],P1,B1); f2(ACC[1][2],P1,B2); f2(ACC[1][3],P1,B3); \
  f2(ACC[2][0],P2,B0); f2(ACC[2][1],P2,B1); f2(ACC[2][2],P2,B2); f2(ACC[2][3],P2,B3); \
  f2(ACC[3][0],P3,B0); f2(ACC[3][1],P3,B1); f2(ACC[3][2],P3,B2); f2(ACC[3][3],P3,B3); \
} while(0)

// -------- K0: rearrange ternary --------
__global__ void k_prep_T(const float* __restrict__ ternary) {
    int idx = blockIdx.x * blockDim.x + threadIdx.x;
    if (idx >= 2*DD*DD*HH) return;
    int c = idx % HH; int t = idx / HH;
    int b = t % DD;   t /= DD;
    int a = t % DD;   int k = t / DD;
    float v = 64.0f * ternary[idx];
    int kc = k*HH + c;
    g_Tr [(kc*DD + a)*DD + b] = v;
    g_Trt[(kc*DD + b)*DD + a] = v;
}

// -------- K1: p = softmax_d(q_z)*mask; writes P and P^T --------
__global__ void k_softmax_p(const float* __restrict__ x, const int* __restrict__ mask, int use_g) {
    int gw = (blockIdx.x * blockDim.x + threadIdx.x) >> 5;
    int lane = threadIdx.x & 31;
    if (gw >= NROW) return;
    int base = gw * DD;
    float v0 = x[base + lane], v1 = x[base + lane + 32];
    if (use_g) {
        #pragma unroll
        for (int g = 0; g < HH; g++) {
            v0 += g_Gpart[g*NELT + base + lane];
            v1 += g_Gpart[g*NELT + base + lane + 32];
        }
        v0 *= (1.0f/64.0f); v1 *= (1.0f/64.0f);
    }
    float m = fmaxf(v0, v1);
    #pragma unroll
    for (int off = 16; off; off >>= 1) m = fmaxf(m, __shfl_xor_sync(0xffffffffu, m, off));
    float e0 = __expf(v0 - m), e1 = __expf(v1 - m);
    float s = e0 + e1;
    #pragma unroll
    for (int off = 16; off; off >>= 1) s += __shfl_xor_sync(0xffffffffu, s, off);
    float mm = (mask[gw] != 0) ? 1.0f : 0.0f;
    float inv = mm / s;
    float p0 = e0 * inv, p1 = e1 * inv;
    g_P[base + lane]      = p0;
    g_P[base + lane + 32] = p1;
    int z = gw >> 9, i = gw & 511;
    g_Pt[(z*DD + lane     )*LL + i] = p0;
    g_Pt[(z*DD + lane + 32)*LL + i] = p1;
}

// -------- K2: fused per-(z,c,i0), 128-row i-tile, two triangle passes --------
extern __shared__ float smf[];
__global__ void __launch_bounds__(256, 2) k_fused() {
    float* sA = smf;                    // A tile [b][128i] SI   (later: W_U)
    float* R0 = smf + 64*SI;            // T / Pj [b][64j] SA / TrtU
    float* R1 = smf + 64*SI + 64*SA;    // Pt / E [j][128i] SI   (later: W_L)
    float* sV = smf + 2*64*SI + 64*SA;  // V [j][64b] SA / TrtL
    int it = blockIdx.x;                // 4 i-tiles of 128 rows
    int i0 = it*128, c = blockIdx.y, z = blockIdx.z;
    int tid = threadIdx.x, tx = tid & 15, ty = tid >> 4;   // ty in [0,16)

    float m[8], ss[8];
    #pragma unroll
    for (int r = 0; r < 8; r++) { m[r] = -1e30f; ss[r] = 0.0f; }
    u64 aU[4][4] = {}, aL[4][4] = {};

    #pragma unroll
    for (int pass = 0; pass < 2; pass++) {
        // ---- A prep: A = Pt_tile(128 cols) @ T[pass?HH+c:c]
        const float* Tsrc = &g_Tr[(pass ? HH + c : c)*DD*DD];
        for (int t = tid; t < 2048; t += 256) {           // Pt [64a][128i]
            int r = t >> 5, q = (t & 31) << 2;
            cpa16(smaddr(&R1[r*SI+q]), &g_Pt[(z*DD + r)*LL + i0 + q]);
        }
        for (int t = tid; t < 1024; t += 256) {           // T [64a][64b]
            int r = t >> 4, q = (t & 15) << 2;
            cpa16(smaddr(&R0[r*SA+q]), &Tsrc[r*DD + q]);
        }
        cpcommit(); cpwait0(); __syncthreads();
        {
            u64 acc[4][4] = {};
            #pragma unroll 8
            for (int a = 0; a < 64; a++) {
                ulonglong2 p01 = *(const ulonglong2*)&R1[a*SI + ty*8];
                ulonglong2 p23 = *(const ulonglong2*)&R1[a*SI + ty*8 + 4];
                float4 fp = *(const float4*)&R0[a*SA + tx*4];
                u64 b0=bc2(fp.x), b1=bc2(fp.y), b2=bc2(fp.z), b3=bc2(fp.w);
                STEP4(acc, p01.x, p01.y, p23.x, p23.y, b0, b1, b2, b3);
            }
            __syncthreads();     // all reads of R0/R1 done
            #pragma unroll
            for (int s = 0; s < 4; s++) {
                float* dst = &sA[(tx*4+s)*SI + ty*8];
                ((ulonglong2*)dst)[0] = make_ulonglong2(acc[0][s], acc[1][s]);
                ((ulonglong2*)dst)[1] = make_ulonglong2(acc[2][s], acc[3][s]);
            }
        }
        __syncthreads();

        int jbeg = pass ? 0 : 2*it;
        int jend = pass ? 2*it + 1 : 7;
        for (int t = tid; t < 1024; t += 256) {     // Pj[jbeg] (own group)
            int r = t >> 4, q = (t & 15) << 2;
            cpa16(smaddr(&R0[r*SA+q]), &g_Pt[(z*DD + r)*LL + jbeg*64 + q]);
        }
        cpcommit();
        for (int t = tid; t < 1024; t += 256) {     // V[jbeg] (own group)
            int r = t >> 4, q = (t & 15) << 2;
            cpa16(smaddr(&sV[r*SA+q]), &g_P[(z*LL + jbeg*64 + r)*DD + q]);
        }
        cpcommit();

        u64 (*aT)[4] = pass ? aL : aU;
        #pragma unroll 1
        for (int jt = jbeg; jt <= jend; jt++) {
            int j0 = jt*64;
            cpwait1(); __syncthreads();             // Pj[jt] ready

            // ---- S GEMM (128i x 64j x 64b)
            u64 acc[4][4] = {};
            #pragma unroll 8
            for (int b = 0; b < 64; b++) {
                ulonglong2 a01 = *(const ulonglong2*)&sA[b*SI + ty*8];
                ulonglong2 a23 = *(const ulonglong2*)&sA[b*SI + ty*8 + 4];
                float4 fp = *(const float4*)&R0[b*SA + tx*4];
                u64 b0=bc2(fp.x), b1=bc2(fp.y), b2=bc2(fp.z), b3=bc2(fp.w);
                STEP4(acc, a01.x, a01.y, a23.x, a23.y, b0, b1, b2, b3);
            }
            __syncthreads();                        // done reading R0
            bool pjnext = (jt < jend);
            if (pjnext) {
                for (int t = tid; t < 1024; t += 256) {
                    int r = t >> 4, q = (t & 15) << 2;
                    cpa16(smaddr(&R0[r*SA+q]), &g_Pt[(z*DD + r)*LL + (jt+1)*64 + q]);
                }
                cpcommit();
            }

            // ---- online-softmax update + E write (diag-band tiles masked)
            bool dg = (jt == 2*it) || (jt == 2*it + 1);
            #pragma unroll
            for (int rp = 0; rp < 4; rp++) {
                float sc0, sc1;
                #pragma unroll
                for (int rr = 0; rr < 2; rr++) {
                    int r = rp*2 + rr;
                    int gil = ty*8 + r;             // local row [0,128)
                    int gig = i0 + gil;             // global row
                    float vv[4];
                    #pragma unroll
                    for (int s = 0; s < 4; s++) {
                        float2 f = up2(acc[rp][s]);
                        vv[s] = rr ? f.y : f.x;
                    }
                    if (dg) {
                        #pragma unroll
                        for (int s = 0; s < 4; s++) {
                            int gjg = j0 + tx*4 + s;
                            if (pass == 0) vv[s] = (gjg > gig) ? vv[s] : (gjg == gig ? 0.0f : -1e30f);
                            else           vv[s] = (gjg < gig) ? vv[s] : -1e30f;
                        }
                    }
                    float tm = fmaxf(fmaxf(vv[0], vv[1]), fmaxf(vv[2], vv[3]));
                    #pragma unroll
                    for (int off = 1; off < 16; off <<= 1)
                        tm = fmaxf(tm, __shfl_xor_sync(0xffffffffu, tm, off));
                    float nm = fmaxf(m[r], tm);
                    float sc = __expf(m[r] - nm);
                    float e0 = __expf(vv[0]-nm), e1 = __expf(vv[1]-nm);
                    float e2 = __expf(vv[2]-nm), e3 = __expf(vv[3]-nm);
                    ss[r] = ss[r]*sc + e0+e1+e2+e3;
                    m[r] = nm;
                    if (rr) sc1 = sc; else sc0 = sc;
                    if (dg && pass == 0) {          // j==i in normalizer, not in W
                        if (j0 + tx*4+0 == gig) e0 = 0.0f;
                        if (j0 + tx*4+1 == gig) e1 = 0.0f;
                        if (j0 + tx*4+2 == gig) e2 = 0.0f;
                        if (j0 + tx*4+3 == gig) e3 = 0.0f;
                    }
                    int ic = gil ^ ((tx & 3) << 3); // XOR swizzle (bits 3,4)
                    R1[(tx*4+0)*SI + ic] = e0;
                    R1[(tx*4+1)*SI + ic] = e1;
                    R1[(tx*4+2)*SI + ic] = e2;
                    R1[(tx*4+3)*SI + ic] = e3;
                }
                u64 sc2 = pk2(sc0, sc1);            // rescale both W accumulators
                #pragma unroll
                for (int s = 0; s < 4; s++) { m2(aU[rp][s], sc2); m2(aL[rp][s], sc2); }
            }
            if (pjnext) cpwait1(); else cpwait0();  // V[jt] ready
            __syncthreads();                        // E visible + V visible

            // ---- W GEMM: E(128i x 64j) @ V(64j x 64b) -> aT
            #pragma unroll 8
            for (int j = 0; j < 64; j++) {
                int base = (ty*8) ^ (((j >> 2) & 3) << 3);
                ulonglong2 p01 = *(const ulonglong2*)&R1[j*SI + base];
                ulonglong2 p23 = *(const ulonglong2*)&R1[j*SI + base + 4];
                float4 fv = *(const float4*)&sV[j*SA + tx*4];
                u64 b0=bc2(fv.x), b1=bc2(fv.y), b2=bc2(fv.z), b3=bc2(fv.w);
                STEP4(aT, p01.x, p01.y, p23.x, p23.y, b0, b1, b2, b3);
            }
            __syncthreads();                        // done reading sV, R1
            if (jt < jend) {
                for (int t = tid; t < 1024; t += 256) {
                    int r = t >> 4, q = (t & 15) << 2;
                    cpa16(smaddr(&sV[r*SA+q]), &g_P[(z*LL + (jt+1)*64 + r)*DD + q]);
                }
                cpcommit();
            }
        }
    }

    // ---- normalize W by 1/sum_exp (shared m across both passes)
    #pragma unroll
    for (int r = 0; r < 8; r++) {
        float sr = ss[r];
        #pragma unroll
        for (int off = 1; off < 16; off <<= 1)
            sr += __shfl_xor_sync(0xffffffffu, sr, off);
        ss[r] = 1.0f / sr;
    }
    #pragma unroll
    for (int rp = 0; rp < 4; rp++) {
        u64 iv2 = pk2(ss[2*rp], ss[2*rp+1]);
        #pragma unroll
        for (int s = 0; s < 4; s++) { m2(aU[rp][s], iv2); m2(aL[rp][s], iv2); }
    }

    // ---- epilogue: G_c = W_U @ Trt[c] + W_L @ Trt[HH+c]
    #pragma unroll
    for (int s = 0; s < 4; s++) {
        float* dU = &sA[(tx*4+s)*SI + ty*8];
        ((ulonglong2*)dU)[0] = make_ulonglong2(aU[0][s], aU[1][s]);
        ((ulonglong2*)dU)[1] = make_ulonglong2(aU[2][s], aU[3][s]);
        float* dL = &R1[(tx*4+s)*SI + ty*8];
        ((ulonglong2*)dL)[0] = make_ulonglong2(aL[0][s], aL[1][s]);
        ((ulonglong2*)dL)[1] = make_ulonglong2(aL[2][s], aL[3][s]);
    }
    for (int t = tid; t < 1024; t += 256) {
        int r = t >> 4, q = (t & 15) << 2;
        *(float4*)&R0[r*SA+q] = *(const float4*)&g_Trt[((c   )*DD + r)*DD + q];
        *(float4*)&sV[r*SA+q] = *(const float4*)&g_Trt[((HH+c)*DD + r)*DD + q];
    }
    __syncthreads();
    u64 acc[4][4] = {};
    #pragma unroll 4
    for (int b = 0; b < 64; b++) {
        ulonglong2 w01 = *(const ulonglong2*)&sA[b*SI + ty*8];
        ulonglong2 w23 = *(const ulonglong2*)&sA[b*SI + ty*8 + 4];
        float4 ft = *(const float4*)&R0[b*SA + tx*4];
        u64 b0=bc2(ft.x), b1=bc2(ft.y), b2=bc2(ft.z), b3=bc2(ft.w);
        STEP4(acc, w01.x, w01.y, w23.x, w23.y, b0, b1, b2, b3);
        ulonglong2 y01 = *(const ulonglong2*)&R1[b*SI + ty*8];
        ulonglong2 y23 = *(const ulonglong2*)&R1[b*SI + ty*8 + 4];
        float4 fl = *(const float4*)&sV[b*SA + tx*4];
        u64 c0=bc2(fl.x), c1=bc2(fl.y), c2=bc2(fl.z), c3=bc2(fl.w);
        STEP4(acc, y01.x, y01.y, y23.x, y23.y, c0, c1, c2, c3);
    }
    #pragma unroll
    for (int rp = 0; rp < 4; rp++) {
        float2 x0 = up2(acc[rp][0]), x1 = up2(acc[rp][1]);
        float2 x2 = up2(acc[rp][2]), x3 = up2(acc[rp][3]);
        int i = i0 + ty*8 + rp*2;
        *(float4*)&g_Gpart[(c*NROW + z*LL + i    )*DD + tx*4] = make_float4(x0.x, x1.x, x2.x, x3.x);
        *(float4*)&g_Gpart[(c*NROW + z*LL + i + 1)*DD + tx*4] = make_float4(x0.y, x1.y, x2.y, x3.y);
    }
}

// -------- K3: out = (x + sum Gpart) / 64 --------
__global__ void k_final(const float* __restrict__ x, float* __restrict__ out) {
    int idx = blockIdx.x * blockDim.x + threadIdx.x;
    if (idx >= NELT) return;
    float v = x[idx];
    #pragma unroll
    for (int g = 0; g < HH; g++) v += g_Gpart[g*NELT + idx];
    out[idx] = v * (1.0f/64.0f);
}

extern "C" void kernel_launch(void* const* d_in, const int* in_sizes, int n_in,
                              void* d_out, int out_size) {
    const float* x       = (const float*)d_in[0];
    const int*   mask    = (const int*)d_in[1];
    const float* ternary = (const float*)d_in[2];
    for (int i = 0; i < n_in; i++) {
        if      (in_sizes[i] == NELT)        x       = (const float*)d_in[i];
        else if (in_sizes[i] == BB*LL)       mask    = (const int*)d_in[i];
        else if (in_sizes[i] == 2*DD*DD*HH)  ternary = (const float*)d_in[i];
    }
    const int SMEM_F = (2*64*SI + 2*64*SA) * 4;   // 102400 B -> 2 blocks/SM
    cudaFuncSetAttribute(k_fused, cudaFuncAttributeMaxDynamicSharedMemorySize, SMEM_F);

    k_prep_T<<<96, 1024>>>(ternary);
    for (int it = 0; it < 4; it++) {
        k_softmax_p<<<NROW/4, 128>>>(x, mask, it > 0 ? 1 : 0);
        k_fused<<<dim3(4, HH, BB), 256, SMEM_F>>>();
    }
    k_final<<<(NELT + 255)/256, 256>>>(x, (float*)d_out);
}

// round 14
// speedup vs baseline: 1.7838x; 1.1670x over previous
#include <cuda_runtime.h>

// HeadProbEncoder: B=8, L=512, d=64, n_head=12, K=2 triangles, 4 iterations.
// Round 14: round-6 champion (triangle-split, online softmax, 3 blocks/SM) +
// (a) log2-domain A scaling so flash exps are bare ex2.approx (no FMUL),
// (b) merged per-tile barriers (4 -> 3), Pj prefetch after the E-write sync.

#define BB 8
#define LL 512
#define DD 64
#define HH 12
#define NROW (BB*LL)
#define NELT (BB*LL*DD)
#define SA 68
#define LOG2E 1.4426950408889634f

typedef unsigned long long u64;

// -------- scratch --------
__device__ float g_P [NELT];          // [z][i][b]
__device__ float g_Pt[BB*DD*LL];      // [z][b][i]
__device__ float g_Tr [2*HH*DD*DD];   // [kc][a][b]
__device__ float g_Trt[2*HH*DD*DD];   // [kc][b][a]
__device__ float g_Gpart[HH*NELT];    // per-c G partials

__device__ __forceinline__ u64 bc2(float v){ u64 r; asm("mov.b64 %0,{%1,%1};":"=l"(r):"f"(v)); return r; }
__device__ __forceinline__ u64 pk2(float lo, float hi){ u64 r; asm("mov.b64 %0,{%1,%2};":"=l"(r):"f"(lo),"f"(hi)); return r; }
__device__ __forceinline__ void f2(u64 &d, u64 a, u64 b){ asm("fma.rn.f32x2 %0,%1,%2,%0;":"+l"(d):"l"(a),"l"(b)); }
__device__ __forceinline__ void m2(u64 &d, u64 s){ asm("mul.rn.f32x2 %0,%0,%1;":"+l"(d):"l"(s)); }
__device__ __forceinline__ float2 up2(u64 v){ float2 f; asm("mov.b64 {%0,%1},%2;":"=f"(f.x),"=f"(f.y):"l"(v)); return f; }
__device__ __forceinline__ float ex2(float x){ float r; asm("ex2.approx.ftz.f32 %0,%1;":"=f"(r):"f"(x)); return r; }
__device__ __forceinline__ unsigned smaddr(const void* p){ return (unsigned)__cvta_generic_to_shared(p); }
__device__ __forceinline__ void cpa16(unsigned s, const void* g){ asm volatile("cp.async.cg.shared.global [%0],[%1],16;"::"r"(s),"l"(g):"memory"); }
__device__ __forceinline__ void cpcommit(){ asm volatile("cp.async.commit_group;":::"memory"); }
__device__ __forceinline__ void cpwait0(){ asm volatile("cp.async.wait_group 0;":::"memory"); }
__device__ __forceinline__ void cpwait1(){ asm volatile("cp.async.wait_group 1;":::"memory"); }

#define STEP4(ACC,P0,P1,P2,P3,B0,B1,B2,B3) do{ \
  f2(ACC[0][0],P0,B0); f2(ACC[0][1],P0,B1); f2(ACC[0][2],P0,B2); f2(ACC[0][3],P0,B3); \
  f2(ACC[1][0],P1,B0); f2(ACC[1][1],P1,B1); f2(ACC[1][2],P1,B2); f2(ACC[1][3],P1,B3); \
  f2(ACC[2][0],P2,B0); f2(ACC[2][1],P2,B1); f2(ACC[2][2],P2,B2); f2(ACC[2][3],P2,B3); \
  f2(ACC[3][0],P3,B0); f2(ACC[3][1],P3,B1); f2(ACC[3][2],P3,B2); f2(ACC[3][3],P3,B3); \
} while(0)

// -------- K0: rearrange ternary --------
__global__ void k_prep_T(const float* __restrict__ ternary) {
    int idx = blockIdx.x * blockDim.x + threadIdx.x;
    if (idx >= 2*DD*DD*HH) return;
    int c = idx % HH; int t = idx / HH;
    int b = t % DD;   t /= DD;
    int a = t % DD;   int k = t / DD;
    float v = 64.0f * ternary[idx];
    int kc = k*HH + c;
    g_Tr [(kc*DD + a)*DD + b] = v;
    g_Trt[(kc*DD + b)*DD + a] = v;
}

// -------- K1: p = softmax_d(q_z)*mask; writes P and P^T --------
__global__ void k_softmax_p(const float* __restrict__ x, const int* __restrict__ mask, int use_g) {
    int gw = (blockIdx.x * blockDim.x + threadIdx.x) >> 5;
    int lane = threadIdx.x & 31;
    if (gw >= NROW) return;
    int base = gw * DD;
    float v0 = x[base + lane], v1 = x[base + lane + 32];
    if (use_g) {
        #pragma unroll
        for (int g = 0; g < HH; g++) {
            v0 += g_Gpart[g*NELT + base + lane];
            v1 += g_Gpart[g*NELT + base + lane + 32];
        }
        v0 *= (1.0f/64.0f); v1 *= (1.0f/64.0f);
    }
    float m = fmaxf(v0, v1);
    #pragma unroll
    for (int off = 16; off; off >>= 1) m = fmaxf(m, __shfl_xor_sync(0xffffffffu, m, off));
    float e0 = __expf(v0 - m), e1 = __expf(v1 - m);
    float s = e0 + e1;
    #pragma unroll
    for (int off = 16; off; off >>= 1) s += __shfl_xor_sync(0xffffffffu, s, off);
    float mm = (mask[gw] != 0) ? 1.0f : 0.0f;
    float inv = mm / s;
    float p0 = e0 * inv, p1 = e1 * inv;
    g_P[base + lane]      = p0;
    g_P[base + lane + 32] = p1;
    int z = gw >> 9, i = gw & 511;
    g_Pt[(z*DD + lane     )*LL + i] = p0;
    g_Pt[(z*DD + lane + 32)*LL + i] = p1;
}

// -------- K2: fused per-(z,c,i0), two triangle passes, log2-domain --------
extern __shared__ float smf[];
__global__ void __launch_bounds__(128, 3) k_fused() {
    float* sA = smf;            // A tile [b][i] (log2-scaled)   (later: W_U)
    float* R0 = smf + 64*SA;    // T / Pj [b][j] / TrtU
    float* R1 = smf + 2*64*SA;  // Pt / E / TrtL
    float* sV = smf + 3*64*SA;  // V [j][b]                      (later: W_L)
    int i0 = blockIdx.x*64, c = blockIdx.y, z = blockIdx.z;
    int it = blockIdx.x;
    int tid = threadIdx.x, tx = tid & 15, ty = tid >> 4;

    float m[8], ss[8];
    #pragma unroll
    for (int r = 0; r < 8; r++) { m[r] = -1e30f; ss[r] = 0.0f; }
    u64 aU[4][4] = {}, aL[4][4] = {};
    const u64 lg2 = bc2(LOG2E);

    #pragma unroll
    for (int pass = 0; pass < 2; pass++) {
        // ---- A prep: A = log2e * (Pt_tile @ T[pass?HH+c:c])
        const float* Tsrc = &g_Tr[(pass ? HH + c : c)*DD*DD];
        for (int t = tid; t < 1024; t += 128) {
            int r = t >> 4, q = (t & 15) << 2;
            cpa16(smaddr(&R1[r*SA+q]), &g_Pt[(z*DD + r)*LL + i0 + q]);
            cpa16(smaddr(&R0[r*SA+q]), &Tsrc[r*DD + q]);
        }
        cpcommit(); cpwait0(); __syncthreads();
        {
            u64 acc[4][4] = {};
            #pragma unroll 8
            for (int a = 0; a < 64; a++) {
                ulonglong2 p01 = *(const ulonglong2*)&R1[a*SA + ty*8];
                ulonglong2 p23 = *(const ulonglong2*)&R1[a*SA + ty*8 + 4];
                float4 fp = *(const float4*)&R0[a*SA + tx*4];
                u64 b0=bc2(fp.x), b1=bc2(fp.y), b2=bc2(fp.z), b3=bc2(fp.w);
                STEP4(acc, p01.x, p01.y, p23.x, p23.y, b0, b1, b2, b3);
            }
            __syncthreads();     // reads of R0/R1 done; sA overwrite safe
            #pragma unroll
            for (int s = 0; s < 4; s++) {
                m2(acc[0][s], lg2); m2(acc[1][s], lg2);
                m2(acc[2][s], lg2); m2(acc[3][s], lg2);
                float* dst = &sA[(tx*4+s)*SA + ty*8];
                ((ulonglong2*)dst)[0] = make_ulonglong2(acc[0][s], acc[1][s]);
                ((ulonglong2*)dst)[1] = make_ulonglong2(acc[2][s], acc[3][s]);
            }
        }
        __syncthreads();

        int jbeg = pass ? 0 : it;
        int jend = pass ? it : 7;
        for (int t = tid; t < 1024; t += 128) {     // Pj[jbeg] (own group)
            int r = t >> 4, q = (t & 15) << 2;
            cpa16(smaddr(&R0[r*SA+q]), &g_Pt[(z*DD + r)*LL + jbeg*64 + q]);
        }
        cpcommit();
        for (int t = tid; t < 1024; t += 128) {     // V[jbeg] (own group)
            int r = t >> 4, q = (t & 15) << 2;
            cpa16(smaddr(&sV[r*SA+q]), &g_P[(z*LL + jbeg*64 + r)*DD + q]);
        }
        cpcommit();

        u64 (*aT)[4] = pass ? aL : aU;
        #pragma unroll 1
        for (int jt = jbeg; jt <= jend; jt++) {
            cpwait1(); __syncthreads();             // Pj[jt] ready (V still in flight)

            // ---- S GEMM (log2-domain scores)
            u64 acc[4][4] = {};
            #pragma unroll 8
            for (int b = 0; b < 64; b++) {
                ulonglong2 a01 = *(const ulonglong2*)&sA[b*SA + ty*8];
                ulonglong2 a23 = *(const ulonglong2*)&sA[b*SA + ty*8 + 4];
                float4 fp = *(const float4*)&R0[b*SA + tx*4];
                u64 b0=bc2(fp.x), b1=bc2(fp.y), b2=bc2(fp.z), b3=bc2(fp.w);
                STEP4(acc, a01.x, a01.y, a23.x, a23.y, b0, b1, b2, b3);
            }

            // ---- online-softmax update (ex2) + E write; no barrier yet
            bool dg = (jt == it);
            float scv[8];
            #pragma unroll
            for (int rp = 0; rp < 4; rp++) {
                #pragma unroll
                for (int rr = 0; rr < 2; rr++) {
                    int r = rp*2 + rr;
                    int gi = ty*8 + r;
                    float vv[4];
                    #pragma unroll
                    for (int s = 0; s < 4; s++) {
                        float2 f = up2(acc[rp][s]);
                        vv[s] = rr ? f.y : f.x;
                    }
                    if (dg) {
                        #pragma unroll
                        for (int s = 0; s < 4; s++) {
                            int gj = tx*4 + s;
                            if (pass == 0) vv[s] = (gj > gi) ? vv[s] : (gj == gi ? 0.0f : -1e30f);
                            else           vv[s] = (gj < gi) ? vv[s] : -1e30f;
                        }
                    }
                    float tm = fmaxf(fmaxf(vv[0], vv[1]), fmaxf(vv[2], vv[3]));
                    #pragma unroll
                    for (int off = 1; off < 16; off <<= 1)
                        tm = fmaxf(tm, __shfl_xor_sync(0xffffffffu, tm, off));
                    float nm = fmaxf(m[r], tm);
                    float sc = ex2(m[r] - nm);
                    float e0 = ex2(vv[0]-nm), e1 = ex2(vv[1]-nm);
                    float e2 = ex2(vv[2]-nm), e3 = ex2(vv[3]-nm);
                    ss[r] = ss[r]*sc + e0+e1+e2+e3;
                    m[r] = nm; scv[r] = sc;
                    if (dg && pass == 0) {          // j==i in normalizer, not in W
                        if (tx*4+0 == gi) e0 = 0.0f;
                        if (tx*4+1 == gi) e1 = 0.0f;
                        if (tx*4+2 == gi) e2 = 0.0f;
                        if (tx*4+3 == gi) e3 = 0.0f;
                    }
                    int ic = gi ^ ((tx & 3) << 3);  // XOR swizzle
                    R1[(tx*4+0)*SA + ic] = e0;
                    R1[(tx*4+1)*SA + ic] = e1;
                    R1[(tx*4+2)*SA + ic] = e2;
                    R1[(tx*4+3)*SA + ic] = e3;
                }
            }
            // rescale both W accumulators (register-only)
            #pragma unroll
            for (int rp = 0; rp < 4; rp++) {
                u64 sc2 = pk2(scv[2*rp], scv[2*rp+1]);
                #pragma unroll
                for (int s = 0; s < 4; s++) { m2(aU[rp][s], sc2); m2(aL[rp][s], sc2); }
            }

            cpwait0();                  // V[jt] arrived (only group in flight)
            __syncthreads();            // publishes E, V visible, R0 reads done

            bool pjnext = (jt < jend);
            if (pjnext) {               // prefetch Pj[jt+1]; overlaps W GEMM
                for (int t = tid; t < 1024; t += 128) {
                    int r = t >> 4, q = (t & 15) << 2;
                    cpa16(smaddr(&R0[r*SA+q]), &g_Pt[(z*DD + r)*LL + (jt+1)*64 + q]);
                }
                cpcommit();
            }

            // ---- W GEMM: E @ V -> aT
            #pragma unroll 8
            for (int j = 0; j < 64; j++) {
                int base = (ty*8) ^ (((j >> 2) & 3) << 3);
                ulonglong2 p01 = *(const ulonglong2*)&R1[j*SA + base];
                ulonglong2 p23 = *(const ulonglong2*)&R1[j*SA + base + 4];
                float4 fv = *(const float4*)&sV[j*SA + tx*4];
                u64 b0=bc2(fv.x), b1=bc2(fv.y), b2=bc2(fv.z), b3=bc2(fv.w);
                STEP4(aT, p01.x, p01.y, p23.x, p23.y, b0, b1, b2, b3);
            }
            __syncthreads();                        // done reading sV, R1
            if (pjnext) {
                for (int t = tid; t < 1024; t += 128) {
                    int r = t >> 4, q = (t & 15) << 2;
                    cpa16(smaddr(&sV[r*SA+q]), &g_P[(z*LL + (jt+1)*64 + r)*DD + q]);
                }
                cpcommit();
            }
        }
    }

    // ---- normalize W by 1/sum_exp
    #pragma unroll
    for (int r = 0; r < 8; r++) {
        float sr = ss[r];
        #pragma unroll
        for (int off = 1; off < 16; off <<= 1)
            sr += __shfl_xor_sync(0xffffffffu, sr, off);
        ss[r] = 1.0f / sr;
    }
    #pragma unroll
    for (int rp = 0; rp < 4; rp++) {
        u64 iv2 = pk2(ss[2*rp], ss[2*rp+1]);
        #pragma unroll
        for (int s = 0; s < 4; s++) { m2(aU[rp][s], iv2); m2(aL[rp][s], iv2); }
    }

    // ---- epilogue: G_c = W_U @ Trt[c] + W_L @ Trt[HH+c]
    #pragma unroll
    for (int s = 0; s < 4; s++) {
        float* dU = &sA[(tx*4+s)*SA + ty*8];
        ((ulonglong2*)dU)[0] = make_ulonglong2(aU[0][s], aU[1][s]);
        ((ulonglong2*)dU)[1] = make_ulonglong2(aU[2][s], aU[3][s]);
        float* dL = &sV[(tx*4+s)*SA + ty*8];
        ((ulonglong2*)dL)[0] = make_ulonglong2(aL[0][s], aL[1][s]);
        ((ulonglong2*)dL)[1] = make_ulonglong2(aL[2][s], aL[3][s]);
    }
    for (int t = tid; t < 1024; t += 128) {
        int r = t >> 4, q = (t & 15) << 2;
        *(float4*)&R0[r*SA+q] = *(const float4*)&g_Trt[((c   )*DD + r)*DD + q];
        *(float4*)&R1[r*SA+q] = *(const float4*)&g_Trt[((HH+c)*DD + r)*DD + q];
    }
    __syncthreads();
    u64 acc[4][4] = {};
    #pragma unroll 4
    for (int b = 0; b < 64; b++) {
        ulonglong2 w01 = *(const ulonglong2*)&sA[b*SA + ty*8];
        ulonglong2 w23 = *(const ulonglong2*)&sA[b*SA + ty*8 + 4];
        float4 ft = *(const float4*)&R0[b*SA + tx*4];
        u64 b0=bc2(ft.x), b1=bc2(ft.y), b2=bc2(ft.z), b3=bc2(ft.w);
        STEP4(acc, w01.x, w01.y, w23.x, w23.y, b0, b1, b2, b3);
        ulonglong2 y01 = *(const ulonglong2*)&sV[b*SA + ty*8];
        ulonglong2 y23 = *(const ulonglong2*)&sV[b*SA + ty*8 + 4];
        float4 fl = *(const float4*)&R1[b*SA + tx*4];
        u64 c0=bc2(fl.x), c1=bc2(fl.y), c2=bc2(fl.z), c3=bc2(fl.w);
        STEP4(acc, y01.x, y01.y, y23.x, y23.y, c0, c1, c2, c3);
    }
    #pragma unroll
    for (int rp = 0; rp < 4; rp++) {
        float2 x0 = up2(acc[rp][0]), x1 = up2(acc[rp][1]);
        float2 x2 = up2(acc[rp][2]), x3 = up2(acc[rp][3]);
        int i = i0 + ty*8 + rp*2;
        *(float4*)&g_Gpart[(c*NROW + z*LL + i    )*DD + tx*4] = make_float4(x0.x, x1.x, x2.x, x3.x);
        *(float4*)&g_Gpart[(c*NROW + z*LL + i + 1)*DD + tx*4] = make_float4(x0.y, x1.y, x2.y, x3.y);
    }
}

// -------- K3: out = (x + sum Gpart) / 64 --------
__global__ void k_final(const float* __restrict__ x, float* __restrict__ out) {
    int idx = blockIdx.x * blockDim.x + threadIdx.x;
    if (idx >= NELT) return;
    float v = x[idx];
    #pragma unroll
    for (int g = 0; g < HH; g++) v += g_Gpart[g*NELT + idx];
    out[idx] = v * (1.0f/64.0f);
}

extern "C" void kernel_launch(void* const* d_in, const int* in_sizes, int n_in,
                              void* d_out, int out_size) {
    const float* x       = (const float*)d_in[0];
    const int*   mask    = (const int*)d_in[1];
    const float* ternary = (const float*)d_in[2];
    for (int i = 0; i < n_in; i++) {
        if      (in_sizes[i] == NELT)        x       = (const float*)d_in[i];
        else if (in_sizes[i] == BB*LL)       mask    = (const int*)d_in[i];
        else if (in_sizes[i] == 2*DD*DD*HH)  ternary = (const float*)d_in[i];
    }
    const int SMEM_F = 4*64*SA*4;   // 69632 B -> 3 blocks/SM
    cudaFuncSetAttribute(k_fused, cudaFuncAttributeMaxDynamicSharedMemorySize, SMEM_F);

    k_prep_T<<<96, 1024>>>(ternary);
    for (int it = 0; it < 4; it++) {
        k_softmax_p<<<NROW/4, 128>>>(x, mask, it > 0 ? 1 : 0);
        k_fused<<<dim3(8, HH, BB), 128, SMEM_F>>>();
    }
    k_final<<<(NELT + 255)/256, 256>>>(x, (float*)d_out);
}

// round 17
// speedup vs baseline: 1.7911x; 1.0041x over previous
#include <cuda_runtime.h>

// HeadProbEncoder: B=8, L=512, d=64, n_head=12, K=2 triangles, 4 iterations.
// Round 15 kernel, third submit (two infra bursts). 3-tile smem (52.2KB ->
// 4 blocks/SM, 16 warps). E overwrites the Pj tile; per-pass retired epilogue
// (unnormalized G_U staged in gmem, combined with telescoped rescale
// ex2(m0-m)) keeps peak regs ~110 under the 128 cap.

#define BB 8
#define LL 512
#define DD 64
#define HH 12
#define NROW (BB*LL)
#define NELT (BB*LL*DD)
#define SA 68
#define LOG2E 1.4426950408889634f

typedef unsigned long long u64;

// -------- scratch --------
__device__ float g_P [NELT];          // [z][i][b]
__device__ float g_Pt[BB*DD*LL];      // [z][b][i]
__device__ float g_Tr [2*HH*DD*DD];   // [kc][a][b]
__device__ float g_Trt[2*HH*DD*DD];   // [kc][b][a]
__device__ float g_Gpart[HH*NELT];    // per-c G partials (staging + final)

__device__ __forceinline__ u64 bc2(float v){ u64 r; asm("mov.b64 %0,{%1,%1};":"=l"(r):"f"(v)); return r; }
__device__ __forceinline__ u64 pk2(float lo, float hi){ u64 r; asm("mov.b64 %0,{%1,%2};":"=l"(r):"f"(lo),"f"(hi)); return r; }
__device__ __forceinline__ void f2(u64 &d, u64 a, u64 b){ asm("fma.rn.f32x2 %0,%1,%2,%0;":"+l"(d):"l"(a),"l"(b)); }
__device__ __forceinline__ void m2(u64 &d, u64 s){ asm("mul.rn.f32x2 %0,%0,%1;":"+l"(d):"l"(s)); }
__device__ __forceinline__ float2 up2(u64 v){ float2 f; asm("mov.b64 {%0,%1},%2;":"=f"(f.x),"=f"(f.y):"l"(v)); return f; }
__device__ __forceinline__ float ex2(float x){ float r; asm("ex2.approx.ftz.f32 %0,%1;":"=f"(r):"f"(x)); return r; }
__device__ __forceinline__ unsigned smaddr(const void* p){ return (unsigned)__cvta_generic_to_shared(p); }
__device__ __forceinline__ void cpa16(unsigned s, const void* g){ asm volatile("cp.async.cg.shared.global [%0],[%1],16;"::"r"(s),"l"(g):"memory"); }
__device__ __forceinline__ void cpcommit(){ asm volatile("cp.async.commit_group;":::"memory"); }
__device__ __forceinline__ void cpwait0(){ asm volatile("cp.async.wait_group 0;":::"memory"); }

#define STEP4(ACC,P0,P1,P2,P3,B0,B1,B2,B3) do{ \
  f2(ACC[0][0],P0,B0); f2(ACC[0][1],P0,B1); f2(ACC[0][2],P0,B2); f2(ACC[0][3],P0,B3); \
  f2(ACC[1][0],P1,B0); f2(ACC[1][1],P1,B1); f2(ACC[1][2],P1,B2); f2(ACC[1][3],P1,B3); \
  f2(ACC[2][0],P2,B0); f2(ACC[2][1],P2,B1); f2(ACC[2][2],P2,B2); f2(ACC[2][3],P2,B3); \
  f2(ACC[3][0],P3,B0); f2(ACC[3][1],P3,B1); f2(ACC[3][2],P3,B2); f2(ACC[3][3],P3,B3); \
} while(0)

// -------- K0: rearrange ternary --------
__global__ void k_prep_T(const float* __restrict__ ternary) {
    int idx = blockIdx.x * blockDim.x + threadIdx.x;
    if (idx >= 2*DD*DD*HH) return;
    int c = idx % HH; int t = idx / HH;
    int b = t % DD;   t /= DD;
    int a = t % DD;   int k = t / DD;
    float v = 64.0f * ternary[idx];
    int kc = k*HH + c;
    g_Tr [(kc*DD + a)*DD + b] = v;
    g_Trt[(kc*DD + b)*DD + a] = v;
}

// -------- K1: p = softmax_d(q_z)*mask; writes P and P^T --------
__global__ void k_softmax_p(const float* __restrict__ x, const int* __restrict__ mask, int use_g) {
    int gw = (blockIdx.x * blockDim.x + threadIdx.x) >> 5;
    int lane = threadIdx.x & 31;
    if (gw >= NROW) return;
    int base = gw * DD;
    float v0 = x[base + lane], v1 = x[base + lane + 32];
    if (use_g) {
        #pragma unroll
        for (int g = 0; g < HH; g++) {
            v0 += g_Gpart[g*NELT + base + lane];
            v1 += g_Gpart[g*NELT + base + lane + 32];
        }
        v0 *= (1.0f/64.0f); v1 *= (1.0f/64.0f);
    }
    float m = fmaxf(v0, v1);
    #pragma unroll
    for (int off = 16; off; off >>= 1) m = fmaxf(m, __shfl_xor_sync(0xffffffffu, m, off));
    float e0 = __expf(v0 - m), e1 = __expf(v1 - m);
    float s = e0 + e1;
    #pragma unroll
    for (int off = 16; off; off >>= 1) s += __shfl_xor_sync(0xffffffffu, s, off);
    float mm = (mask[gw] != 0) ? 1.0f : 0.0f;
    float inv = mm / s;
    float p0 = e0 * inv, p1 = e1 * inv;
    g_P[base + lane]      = p0;
    g_P[base + lane + 32] = p1;
    int z = gw >> 9, i = gw & 511;
    g_Pt[(z*DD + lane     )*LL + i] = p0;
    g_Pt[(z*DD + lane + 32)*LL + i] = p1;
}

// -------- K2: fused, 3-tile smem, per-pass retired epilogue --------
extern __shared__ float smf[];
__global__ void __launch_bounds__(128, 4) k_fused() {
    float* T0 = smf;            // A tile [b][i] log2-scaled; later W [b][i]
    float* T1 = smf + 64*SA;    // Pt(prep a) / Pj / E / Trt
    float* T2 = smf + 2*64*SA;  // T(prep b) / V
    int i0 = blockIdx.x*64, c = blockIdx.y, z = blockIdx.z;
    int it = blockIdx.x;
    int tid = threadIdx.x, tx = tid & 15, ty = tid >> 4;

    float m[8], ss[8], m0s[8];
    #pragma unroll
    for (int r = 0; r < 8; r++) { m[r] = -1e30f; ss[r] = 0.0f; }
    u64 aW[4][4] = {};
    const u64 lg2 = bc2(LOG2E);

    #pragma unroll 1
    for (int pass = 0; pass < 2; pass++) {
        // ---- A prep: A = log2e * (Pt_tile @ T[pass?HH+c:c])
        const float* Tsrc = &g_Tr[(pass ? HH + c : c)*DD*DD];
        for (int t = tid; t < 1024; t += 128) {
            int r = t >> 4, q = (t & 15) << 2;
            cpa16(smaddr(&T1[r*SA+q]), &g_Pt[(z*DD + r)*LL + i0 + q]);
            cpa16(smaddr(&T2[r*SA+q]), &Tsrc[r*DD + q]);
        }
        cpcommit(); cpwait0(); __syncthreads();
        {
            u64 acc[4][4] = {};
            #pragma unroll 8
            for (int a = 0; a < 64; a++) {
                ulonglong2 p01 = *(const ulonglong2*)&T1[a*SA + ty*8];
                ulonglong2 p23 = *(const ulonglong2*)&T1[a*SA + ty*8 + 4];
                float4 fp = *(const float4*)&T2[a*SA + tx*4];
                u64 b0=bc2(fp.x), b1=bc2(fp.y), b2=bc2(fp.z), b3=bc2(fp.w);
                STEP4(acc, p01.x, p01.y, p23.x, p23.y, b0, b1, b2, b3);
            }
            __syncthreads();     // reads of T1/T2 done
            #pragma unroll
            for (int s = 0; s < 4; s++) {
                m2(acc[0][s], lg2); m2(acc[1][s], lg2);
                m2(acc[2][s], lg2); m2(acc[3][s], lg2);
                float* dst = &T0[(tx*4+s)*SA + ty*8];
                ((ulonglong2*)dst)[0] = make_ulonglong2(acc[0][s], acc[1][s]);
                ((ulonglong2*)dst)[1] = make_ulonglong2(acc[2][s], acc[3][s]);
            }
        }
        int jbeg = pass ? 0 : it;
        int jend = pass ? it : 7;
        for (int t = tid; t < 1024; t += 128) {     // Pj[jbeg], V[jbeg]
            int r = t >> 4, q = (t & 15) << 2;
            cpa16(smaddr(&T1[r*SA+q]), &g_Pt[(z*DD + r)*LL + jbeg*64 + q]);
            cpa16(smaddr(&T2[r*SA+q]), &g_P[(z*LL + jbeg*64 + r)*DD + q]);
        }
        cpcommit();

        #pragma unroll 1
        for (int jt = jbeg; jt <= jend; jt++) {
            cpwait0(); __syncthreads();             // Pj,V ready; T0(A) visible

            // ---- S GEMM (log2-domain scores)
            u64 acc[4][4] = {};
            #pragma unroll 8
            for (int b = 0; b < 64; b++) {
                ulonglong2 a01 = *(const ulonglong2*)&T0[b*SA + ty*8];
                ulonglong2 a23 = *(const ulonglong2*)&T0[b*SA + ty*8 + 4];
                float4 fp = *(const float4*)&T1[b*SA + tx*4];
                u64 b0=bc2(fp.x), b1=bc2(fp.y), b2=bc2(fp.z), b3=bc2(fp.w);
                STEP4(acc, a01.x, a01.y, a23.x, a23.y, b0, b1, b2, b3);
            }
            __syncthreads();                        // Pj reads done; E may overwrite T1

            // ---- online-softmax update (ex2) + E write into T1
            bool dg = (jt == it);
            float scv[8];
            #pragma unroll
            for (int rp = 0; rp < 4; rp++) {
                #pragma unroll
                for (int rr = 0; rr < 2; rr++) {
                    int r = rp*2 + rr;
                    int gi = ty*8 + r;
                    float vv[4];
                    #pragma unroll
                    for (int s = 0; s < 4; s++) {
                        float2 f = up2(acc[rp][s]);
                        vv[s] = rr ? f.y : f.x;
                    }
                    if (dg) {
                        #pragma unroll
                        for (int s = 0; s < 4; s++) {
                            int gj = tx*4 + s;
                            if (pass == 0) vv[s] = (gj > gi) ? vv[s] : (gj == gi ? 0.0f : -1e30f);
                            else           vv[s] = (gj < gi) ? vv[s] : -1e30f;
                        }
                    }
                    float tm = fmaxf(fmaxf(vv[0], vv[1]), fmaxf(vv[2], vv[3]));
                    #pragma unroll
                    for (int off = 1; off < 16; off <<= 1)
                        tm = fmaxf(tm, __shfl_xor_sync(0xffffffffu, tm, off));
                    float nm = fmaxf(m[r], tm);
                    float sc = ex2(m[r] - nm);
                    float e0 = ex2(vv[0]-nm), e1 = ex2(vv[1]-nm);
                    float e2 = ex2(vv[2]-nm), e3 = ex2(vv[3]-nm);
                    ss[r] = ss[r]*sc + e0+e1+e2+e3;
                    m[r] = nm; scv[r] = sc;
                    if (dg && pass == 0) {          // j==i in normalizer, not in W
                        if (tx*4+0 == gi) e0 = 0.0f;
                        if (tx*4+1 == gi) e1 = 0.0f;
                        if (tx*4+2 == gi) e2 = 0.0f;
                        if (tx*4+3 == gi) e3 = 0.0f;
                    }
                    int ic = gi ^ ((tx & 3) << 3);  // XOR swizzle
                    T1[(tx*4+0)*SA + ic] = e0;
                    T1[(tx*4+1)*SA + ic] = e1;
                    T1[(tx*4+2)*SA + ic] = e2;
                    T1[(tx*4+3)*SA + ic] = e3;
                }
            }
            #pragma unroll
            for (int rp = 0; rp < 4; rp++) {        // rescale W accumulator
                u64 sc2 = pk2(scv[2*rp], scv[2*rp+1]);
                #pragma unroll
                for (int s = 0; s < 4; s++) m2(aW[rp][s], sc2);
            }
            __syncthreads();                        // E visible

            // ---- W GEMM: E(T1) @ V(T2) -> aW
            #pragma unroll 8
            for (int j = 0; j < 64; j++) {
                int base = (ty*8) ^ (((j >> 2) & 3) << 3);
                ulonglong2 p01 = *(const ulonglong2*)&T1[j*SA + base];
                ulonglong2 p23 = *(const ulonglong2*)&T1[j*SA + base + 4];
                float4 fv = *(const float4*)&T2[j*SA + tx*4];
                u64 b0=bc2(fv.x), b1=bc2(fv.y), b2=bc2(fv.z), b3=bc2(fv.w);
                STEP4(aW, p01.x, p01.y, p23.x, p23.y, b0, b1, b2, b3);
            }
            __syncthreads();                        // T1/T2 reads done
            if (jt < jend) {
                for (int t = tid; t < 1024; t += 128) {
                    int r = t >> 4, q = (t & 15) << 2;
                    cpa16(smaddr(&T1[r*SA+q]), &g_Pt[(z*DD + r)*LL + (jt+1)*64 + q]);
                    cpa16(smaddr(&T2[r*SA+q]), &g_P[(z*LL + (jt+1)*64 + r)*DD + q]);
                }
                cpcommit();
            }
        }

        // ---- per-pass epilogue: retire aW -> G partial
        // W (unnormalized) -> T0; Trt -> T1
        #pragma unroll
        for (int s = 0; s < 4; s++) {
            float* dW = &T0[(tx*4+s)*SA + ty*8];
            ((ulonglong2*)dW)[0] = make_ulonglong2(aW[0][s], aW[1][s]);
            ((ulonglong2*)dW)[1] = make_ulonglong2(aW[2][s], aW[3][s]);
        }
        for (int t = tid; t < 1024; t += 128) {
            int r = t >> 4, q = (t & 15) << 2;
            cpa16(smaddr(&T1[r*SA+q]), &g_Trt[((pass ? HH + c : c)*DD + r)*DD + q]);
        }
        cpcommit(); cpwait0(); __syncthreads();     // W visible + Trt ready
        u64 ag[4][4] = {};
        #pragma unroll 8
        for (int b = 0; b < 64; b++) {
            ulonglong2 w01 = *(const ulonglong2*)&T0[b*SA + ty*8];
            ulonglong2 w23 = *(const ulonglong2*)&T0[b*SA + ty*8 + 4];
            float4 ft = *(const float4*)&T1[b*SA + tx*4];
            u64 b0=bc2(ft.x), b1=bc2(ft.y), b2=bc2(ft.z), b3=bc2(ft.w);
            STEP4(ag, w01.x, w01.y, w23.x, w23.y, b0, b1, b2, b3);
        }
        if (pass == 0) {
            // stage unnormalized G_U; save m0; reset aW for pass 1
            #pragma unroll
            for (int rp = 0; rp < 4; rp++) {
                float2 x0 = up2(ag[rp][0]), x1 = up2(ag[rp][1]);
                float2 x2 = up2(ag[rp][2]), x3 = up2(ag[rp][3]);
                int i = i0 + ty*8 + rp*2;
                *(float4*)&g_Gpart[(c*NROW + z*LL + i    )*DD + tx*4] = make_float4(x0.x, x1.x, x2.x, x3.x);
                *(float4*)&g_Gpart[(c*NROW + z*LL + i + 1)*DD + tx*4] = make_float4(x0.y, x1.y, x2.y, x3.y);
            }
            #pragma unroll
            for (int r = 0; r < 8; r++) m0s[r] = m[r];
            #pragma unroll
            for (int rp = 0; rp < 4; rp++)
                #pragma unroll
                for (int s = 0; s < 4; s++) aW[rp][s] = 0ULL;
            __syncthreads();            // T0/T1 reads done before pass-1 reuse
        } else {
            // final combine: G = G_U * ex2(m0-m)*inv + G_L * inv
            float inv[8], fU[8];
            #pragma unroll
            for (int r = 0; r < 8; r++) {
                float sr = ss[r];
                #pragma unroll
                for (int off = 1; off < 16; off <<= 1)
                    sr += __shfl_xor_sync(0xffffffffu, sr, off);
                inv[r] = 1.0f / sr;
                fU[r] = ex2(m0s[r] - m[r]) * inv[r];
            }
            #pragma unroll
            for (int rp = 0; rp < 4; rp++) {
                float2 x0 = up2(ag[rp][0]), x1 = up2(ag[rp][1]);
                float2 x2 = up2(ag[rp][2]), x3 = up2(ag[rp][3]);
                int i = i0 + ty*8 + rp*2;
                float* pA = &g_Gpart[(c*NROW + z*LL + i    )*DD + tx*4];
                float* pB = &g_Gpart[(c*NROW + z*LL + i + 1)*DD + tx*4];
                float4 guA = *(float4*)pA;
                float4 guB = *(float4*)pB;
                float fa = fU[2*rp], na = inv[2*rp];
                float fb = fU[2*rp+1], nb = inv[2*rp+1];
                *(float4*)pA = make_float4(guA.x*fa + x0.x*na, guA.y*fa + x1.x*na,
                                           guA.z*fa + x2.x*na, guA.w*fa + x3.x*na);
                *(float4*)pB = make_float4(guB.x*fb + x0.y*nb, guB.y*fb + x1.y*nb,
                                           guB.z*fb + x2.y*nb, guB.w*fb + x3.y*nb);
            }
        }
    }
}

// -------- K3: out = (x + sum Gpart) / 64 --------
__global__ void k_final(const float* __restrict__ x, float* __restrict__ out) {
    int idx = blockIdx.x * blockDim.x + threadIdx.x;
    if (idx >= NELT) return;
    float v = x[idx];
    #pragma unroll
    for (int g = 0; g < HH; g++) v += g_Gpart[g*NELT + idx];
    out[idx] = v * (1.0f/64.0f);
}

extern "C" void kernel_launch(void* const* d_in, const int* in_sizes, int n_in,
                              void* d_out, int out_size) {
    const float* x       = (const float*)d_in[0];
    const int*   mask    = (const int*)d_in[1];
    const float* ternary = (const float*)d_in[2];
    for (int i = 0; i < n_in; i++) {
        if      (in_sizes[i] == NELT)        x       = (const float*)d_in[i];
        else if (in_sizes[i] == BB*LL)       mask    = (const int*)d_in[i];
        else if (in_sizes[i] == 2*DD*DD*HH)  ternary = (const float*)d_in[i];
    }
    const int SMEM_F = 3*64*SA*4;   // 52224 B -> 4 blocks/SM
    cudaFuncSetAttribute(k_fused, cudaFuncAttributeMaxDynamicSharedMemorySize, SMEM_F);

    k_prep_T<<<96, 1024>>>(ternary);
    for (int it = 0; it < 4; it++) {
        k_softmax_p<<<NROW/4, 128>>>(x, mask, it > 0 ? 1 : 0);
        k_fused<<<dim3(8, HH, BB), 128, SMEM_F>>>();
    }
    k_final<<<(NELT + 255)/256, 256>>>(x, (float*)d_out);
}